// round 4
// baseline (speedup 1.0000x reference)
#include <cuda_runtime.h>
#include <cuda_bf16.h>
#include <cstdint>
#include <cstddef>

// ---------------------------------------------------------------------------
// Problem constants
// ---------------------------------------------------------------------------
#define Bsz    8192
#define Tlen   64
#define MAXL   64
#define Cvoc   128
#define Hd     50
#define Ldim   20
#define NS     56                 // samples per block
#define TPB    448                // 56 * 8
#define NBLK   147                // ceil(8192/56)

#define WORDS_ELEMS (Bsz * MAXL * Cvoc)        // 67,108,864
#define MU_OFF      ((size_t)WORDS_ELEMS)
#define LV_OFF      (MU_OFF + (size_t)Bsz * Ldim)

// ---------------------------------------------------------------------------
// Device scratch (static __device__ arrays: allocation-free)
// ---------------------------------------------------------------------------
__device__ float g_encf[Cvoc * 152];          // bih_f + embed_enc[c] @ Wih_f.T
__device__ float g_dect[Cvoc * 152];          // silu(embed_dec[c]) @ Wih1[:, :50].T
__device__ float g_bh  [Cvoc * 52];           // backward-cell output per token (h0 = 0)
__device__ float g_giz [(size_t)Bsz * 152];   // bih1 + z @ Wih1[:, 50:70].T
__device__ float g_outz[(size_t)Bsz * 128];   // bh2o + z @ Wh2o[:, 50:70].T

// ---------------------------------------------------------------------------
// Shared memory layout (floats). Total = 53672 floats = 214,688 B
// ---------------------------------------------------------------------------
#define oW1 0                    // 152x52   Whh_f (enc) -> Whh1 (dec)
#define oW2 7904                 // 152x52   Wih2
#define oW3 15808                // 152x52   Whh2
#define oWO 23712                // 128x52   Wh2o[:, :50]
#define oB1 30368                // 152      bhh_f -> bhh1
#define oB2 30520                // 152      bih2
#define oB3 30672                // 152      bhh2
#define oH1 30824                // 56x52
#define oH2 33736                // 56x52
#define oGA 36648                // 56x152
#define oGB 45160                // 56x152
#define SMEM_FLOATS 53672
#define SMEM_BYTES  (SMEM_FLOATS * 4)

// ---------------------------------------------------------------------------
// f32x2 packed FMA helpers
// ---------------------------------------------------------------------------
__device__ __forceinline__ unsigned long long fma2(unsigned long long a,
                                                   unsigned long long b,
                                                   unsigned long long c) {
    unsigned long long d;
    asm("fma.rn.f32x2 %0, %1, %2, %3;" : "=l"(d) : "l"(a), "l"(b), "l"(c));
    return d;
}
__device__ __forceinline__ float2 u2f(unsigned long long v) {
    float2 f;
    asm("mov.b64 {%0, %1}, %2;" : "=f"(f.x), "=f"(f.y) : "l"(v));
    return f;
}
__device__ __forceinline__ float sigm(float x) { return 1.0f / (1.0f + expf(-x)); }

// 152-row matvec over a 50(+2 pad)-vector in smem. Thread r owns rows r, r+8, ...
// h pads [50..51] are zero, so weight pad columns never contribute.
__device__ __forceinline__ void matvec152(const float* __restrict__ Wsm,
                                          const float* __restrict__ hvec,
                                          const float* __restrict__ bias,
                                          int r, float* __restrict__ outv) {
    unsigned long long acc[19];
#pragma unroll
    for (int i = 0; i < 19; i++) acc[i] = 0ull;
    const ulonglong2* h2 = reinterpret_cast<const ulonglong2*>(hvec);
#pragma unroll 1
    for (int j = 0; j < 13; j++) {
        ulonglong2 hv = h2[j];
#pragma unroll
        for (int i = 0; i < 19; i++) {
            ulonglong2 wv = *reinterpret_cast<const ulonglong2*>(Wsm + (r + 8 * i) * 52 + j * 4);
            acc[i] = fma2(wv.x, hv.x, acc[i]);
            acc[i] = fma2(wv.y, hv.y, acc[i]);
        }
    }
#pragma unroll
    for (int i = 0; i < 19; i++) {
        float2 f = u2f(acc[i]);
        outv[r + 8 * i] = f.x + f.y + bias[r + 8 * i];
    }
}

// ---------------------------------------------------------------------------
// Precompute kernel: per-token tables. Grid = 128 blocks (one per token), 160 thr.
// ---------------------------------------------------------------------------
__global__ void vae_pre(const float* __restrict__ embed_enc,
                        const float* __restrict__ Wih_f, const float* __restrict__ bih_f,
                        const float* __restrict__ Wih_b, const float* __restrict__ bih_b,
                        const float* __restrict__ bhh_b,
                        const float* __restrict__ embed_dec,
                        const float* __restrict__ Wih1) {
    __shared__ float ee[50];
    __shared__ float ed[50];
    int c = blockIdx.x;
    int t = threadIdx.x;
    if (t < 50) {
        ee[t] = embed_enc[c * 50 + t];
        float e = embed_dec[c * 50 + t];
        ed[t] = e / (1.0f + expf(-e));      // silu
    }
    __syncthreads();

    if (t < 152) {
        float a = 0.0f, d = 0.0f;
        if (t < 150) {
            a = bih_f[t];
            for (int j = 0; j < 50; j++) {
                a = fmaf(ee[j], Wih_f[t * 50 + j], a);
                d = fmaf(ed[j], Wih1[t * 70 + j], d);
            }
        }
        g_encf[c * 152 + t] = a;
        g_dect[c * 152 + t] = d;
    }
    if (t < 52) {
        float hv = 0.0f;
        if (t < 50) {
            float gr = bih_b[t], gz = bih_b[50 + t], gn = bih_b[100 + t];
            for (int j = 0; j < 50; j++) {
                float e = ee[j];
                gr = fmaf(e, Wih_b[t * 50 + j], gr);
                gz = fmaf(e, Wih_b[(50 + t) * 50 + j], gz);
                gn = fmaf(e, Wih_b[(100 + t) * 50 + j], gn);
            }
            float rr = sigm(gr + bhh_b[t]);
            float zz = sigm(gz + bhh_b[50 + t]);
            float nn = tanhf(gn + rr * bhh_b[100 + t]);
            hv = (1.0f - zz) * nn;          // h0 = 0  =>  h' = (1-z)*n
        }
        g_bh[c * 52 + t] = hv;
    }
}

// ---------------------------------------------------------------------------
// Main fused kernel: encoder (64 GRU steps) + tail + decoder (64 steps)
// ---------------------------------------------------------------------------
__global__ void __launch_bounds__(TPB, 1)
vae_main(const int* __restrict__ x,
         const float* __restrict__ Whh_f, const float* __restrict__ bhh_f,
         const float* __restrict__ Wh2p,  const float* __restrict__ bh2p,
         const float* __restrict__ Wz2h,  const float* __restrict__ bz2h,
         const float* __restrict__ Wih1,  const float* __restrict__ bih1,
         const float* __restrict__ Whh1,  const float* __restrict__ bhh1,
         const float* __restrict__ Wih2,  const float* __restrict__ bih2,
         const float* __restrict__ Whh2,  const float* __restrict__ bhh2,
         const float* __restrict__ Wh2o,  const float* __restrict__ bh2o,
         float* __restrict__ out) {
    extern __shared__ float sm[];
    const int tid = threadIdx.x;
    const int s   = tid >> 3;
    const int r   = tid & 7;
    const int b   = blockIdx.x * NS + s;
    const int bc  = (b < Bsz) ? b : (Bsz - 1);
    const bool valid = (b < Bsz);

    float* W1  = sm + oW1;
    float* W2  = sm + oW2;
    float* W3  = sm + oW3;
    float* WO  = sm + oWO;
    float* B1  = sm + oB1;
    float* B2  = sm + oB2;
    float* B3  = sm + oB3;
    float* h1s = sm + oH1 + s * 52;
    float* h2s = sm + oH2 + s * 52;
    float* GAs = sm + oGA + s * 152;
    float* GBs = sm + oGB + s * 152;

    // ---- load encoder weights; init hidden state ----
    for (int i = tid; i < 152 * 52; i += TPB) {
        int row = i / 52, j = i % 52;
        W1[i] = (row < 150 && j < 50) ? Whh_f[row * 50 + j] : 0.0f;
    }
    for (int i = tid; i < 152; i += TPB) B1[i] = (i < 150) ? bhh_f[i] : 0.0f;
#pragma unroll
    for (int k = 0; k < 7; k++) {
        int u = r + 8 * k;
        if (u < 52) { h1s[u] = 0.0f; h2s[u] = 0.0f; }
    }
    __syncthreads();

    // ================= ENCODER: 64 forward GRU steps =================
    for (int t = 0; t < Tlen; t++) {
        int c = __ldg(&x[bc * Tlen + t]);
        matvec152(W1, h1s, B1, r, GBs);                       // gh = h@Whh_f.T + bhh_f
        __syncwarp();
        const float* T = &g_encf[(size_t)c * 152];
#pragma unroll
        for (int k = 0; k < 7; k++) {
            int u = r + 8 * k;
            if (u < 50) {
                float rr = sigm(__ldg(T + u)       + GBs[u]);
                float zz = sigm(__ldg(T + 50 + u)  + GBs[50 + u]);
                float nn = tanhf(__ldg(T + 100 + u) + rr * GBs[100 + u]);
                h1s[u] = (1.0f - zz) * nn + zz * h1s[u];
            }
        }
        __syncwarp();
    }

    // ---- add backward cell (pure table lookup) ----
    {
        int clast = __ldg(&x[bc * Tlen + Tlen - 1]);
#pragma unroll
        for (int k = 0; k < 7; k++) {
            int u = r + 8 * k;
            if (u < 50) h1s[u] += __ldg(&g_bh[clast * 52 + u]);
        }
        __syncwarp();
    }

    // ---- p = h_enc@Wh2p.T + bh2p ; mu/logvar out ; z = mu into GA[0:20] ----
#pragma unroll
    for (int k = 0; k < 5; k++) {
        int row = r + 8 * k;
        if (row < 40) {
            float acc = __ldg(&bh2p[row]);
            for (int j = 0; j < 50; j++)
                acc = fmaf(__ldg(&Wh2p[row * 50 + j]), h1s[j], acc);
            if (row < 20) {
                GAs[row] = acc;
                if (valid) out[MU_OFF + (size_t)b * Ldim + row] = acc;
            } else {
                if (valid) out[LV_OFF + (size_t)b * Ldim + (row - 20)] = acc;
            }
        }
    }
    __syncwarp();

    // ---- h_init, giz, outz (per-sample constants for the rollout) ----
#pragma unroll
    for (int k = 0; k < 7; k++) {
        int u = r + 8 * k;
        if (u < 50) {
            float acc = __ldg(&bz2h[u]);
            for (int l = 0; l < 20; l++)
                acc = fmaf(__ldg(&Wz2h[u * 20 + l]), GAs[l], acc);
            h1s[u] = acc;
            h2s[u] = acc;
        }
    }
    for (int k = 0; k < 19; k++) {
        int row = r + 8 * k;
        if (row < 150) {
            float acc = __ldg(&bih1[row]);
            for (int l = 0; l < 20; l++)
                acc = fmaf(__ldg(&Wih1[row * 70 + 50 + l]), GAs[l], acc);
            g_giz[(size_t)bc * 152 + row] = acc;
        }
    }
#pragma unroll
    for (int k = 0; k < 16; k++) {
        int row = r + 8 * k;
        float acc = __ldg(&bh2o[row]);
        for (int l = 0; l < 20; l++)
            acc = fmaf(__ldg(&Wh2o[row * 70 + 50 + l]), GAs[l], acc);
        g_outz[(size_t)bc * 128 + row] = acc;
    }
    __syncthreads();

    // ---- swap smem to decoder weights ----
    for (int i = tid; i < 152 * 52; i += TPB) {
        int row = i / 52, j = i % 52;
        bool ok = (row < 150 && j < 50);
        W1[i] = ok ? Whh1[row * 50 + j] : 0.0f;
        W2[i] = ok ? Wih2[row * 50 + j] : 0.0f;
        W3[i] = ok ? Whh2[row * 50 + j] : 0.0f;
    }
    for (int i = tid; i < 128 * 52; i += TPB) {
        int row = i / 52, j = i % 52;
        WO[i] = (j < 50) ? Wh2o[row * 70 + j] : 0.0f;
    }
    for (int i = tid; i < 152; i += TPB) {
        bool ok = (i < 150);
        B1[i] = ok ? bhh1[i] : 0.0f;
        B2[i] = ok ? bih2[i] : 0.0f;
        B3[i] = ok ? bhh2[i] : 0.0f;
    }
    __syncthreads();

    // ================= DECODER: 64 autoregressive steps =================
    int c = 1;  // SOS
    const float* GIZ = &g_giz[(size_t)bc * 152];
    for (int t = 0; t < MAXL; t++) {
        // layer-1: gh1
        matvec152(W1, h1s, B1, r, GBs);
        __syncwarp();
        {
            const float* T = &g_dect[(size_t)c * 152];
#pragma unroll
            for (int k = 0; k < 7; k++) {
                int u = r + 8 * k;
                if (u < 50) {
                    float gir = __ldg(T + u)        + __ldg(GIZ + u);
                    float giz_= __ldg(T + 50 + u)   + __ldg(GIZ + 50 + u);
                    float gin = __ldg(T + 100 + u)  + __ldg(GIZ + 100 + u);
                    float rr = sigm(gir  + GBs[u]);
                    float zz = sigm(giz_ + GBs[50 + u]);
                    float nn = tanhf(gin + rr * GBs[100 + u]);
                    h1s[u] = (1.0f - zz) * nn + zz * h1s[u];
                }
            }
        }
        __syncwarp();
        // layer-2: gi2 (from new h1) and gh2 (from old h2)
        matvec152(W2, h1s, B2, r, GAs);
        matvec152(W3, h2s, B3, r, GBs);
        __syncwarp();
#pragma unroll
        for (int k = 0; k < 7; k++) {
            int u = r + 8 * k;
            if (u < 50) {
                float rr = sigm(GAs[u] + GBs[u]);
                float zz = sigm(GAs[50 + u] + GBs[50 + u]);
                float nn = tanhf(GAs[100 + u] + rr * GBs[100 + u]);
                h2s[u] = (1.0f - zz) * nn + zz * h2s[u];
            }
        }
        __syncwarp();

        // output projection (rows r+8k, k<16) kept in registers
        float vals[16];
        {
            unsigned long long acc[16];
#pragma unroll
            for (int i = 0; i < 16; i++) acc[i] = 0ull;
            const ulonglong2* h2v = reinterpret_cast<const ulonglong2*>(h2s);
#pragma unroll 1
            for (int j = 0; j < 13; j++) {
                ulonglong2 hv = h2v[j];
#pragma unroll
                for (int i = 0; i < 16; i++) {
                    ulonglong2 wv = *reinterpret_cast<const ulonglong2*>(WO + (r + 8 * i) * 52 + j * 4);
                    acc[i] = fma2(wv.x, hv.x, acc[i]);
                    acc[i] = fma2(wv.y, hv.y, acc[i]);
                }
            }
#pragma unroll
            for (int i = 0; i < 16; i++) {
                float2 f = u2f(acc[i]);
                vals[i] = f.x + f.y + __ldg(&g_outz[(size_t)bc * 128 + r + 8 * i]);
            }
        }

        // argmax (first-occurrence ties) + logsumexp across the sample's 8 lanes
        float m = vals[0];
        int   mi = r;
#pragma unroll
        for (int k = 1; k < 16; k++) {
            if (vals[k] > m) { m = vals[k]; mi = r + 8 * k; }
        }
#pragma unroll
        for (int o = 4; o >= 1; o >>= 1) {
            float m2 = __shfl_xor_sync(0xffffffffu, m, o);
            int   i2 = __shfl_xor_sync(0xffffffffu, mi, o);
            if (m2 > m || (m2 == m && i2 < mi)) { m = m2; mi = i2; }
        }
        float ssum = 0.0f;
#pragma unroll
        for (int k = 0; k < 16; k++) ssum += __expf(vals[k] - m);
#pragma unroll
        for (int o = 4; o >= 1; o >>= 1)
            ssum += __shfl_xor_sync(0xffffffffu, ssum, o);
        float lse = m + logf(ssum);
        c = mi;

        if (valid) {
            float* wout = out + (size_t)b * (MAXL * Cvoc) + (size_t)t * Cvoc;
#pragma unroll
            for (int k = 0; k < 16; k++) wout[r + 8 * k] = vals[k] - lse;
        }
    }
}

// ---------------------------------------------------------------------------
// Launch
// ---------------------------------------------------------------------------
extern "C" void kernel_launch(void* const* d_in, const int* in_sizes, int n_in,
                              void* d_out, int out_size) {
    const int*   x         = (const int*)  d_in[0];
    const float* embed_enc = (const float*)d_in[1];
    const float* Wih_f     = (const float*)d_in[2];
    const float* Whh_f     = (const float*)d_in[3];
    const float* bih_f     = (const float*)d_in[4];
    const float* bhh_f     = (const float*)d_in[5];
    const float* Wih_b     = (const float*)d_in[6];
    const float* Whh_b     = (const float*)d_in[7];  (void)Whh_b;  // h0=0: unused
    const float* bih_b     = (const float*)d_in[8];
    const float* bhh_b     = (const float*)d_in[9];
    const float* Wh2p      = (const float*)d_in[10];
    const float* bh2p      = (const float*)d_in[11];
    const float* embed_dec = (const float*)d_in[12];
    const float* Wz2h      = (const float*)d_in[13];
    const float* bz2h      = (const float*)d_in[14];
    const float* Wih1      = (const float*)d_in[15];
    const float* Whh1      = (const float*)d_in[16];
    const float* bih1      = (const float*)d_in[17];
    const float* bhh1      = (const float*)d_in[18];
    const float* Wih2      = (const float*)d_in[19];
    const float* Whh2      = (const float*)d_in[20];
    const float* bih2      = (const float*)d_in[21];
    const float* bhh2      = (const float*)d_in[22];
    const float* Wh2o      = (const float*)d_in[23];
    const float* bh2o      = (const float*)d_in[24];
    float* out = (float*)d_out;

    cudaFuncSetAttribute(vae_main, cudaFuncAttributeMaxDynamicSharedMemorySize, SMEM_BYTES);

    vae_pre<<<Cvoc, 160>>>(embed_enc, Wih_f, bih_f, Wih_b, bih_b, bhh_b, embed_dec, Wih1);
    vae_main<<<NBLK, TPB, SMEM_BYTES>>>(x,
                                        Whh_f, bhh_f, Wh2p, bh2p, Wz2h, bz2h,
                                        Wih1, bih1, Whh1, bhh1, Wih2, bih2,
                                        Whh2, bhh2, Wh2o, bh2o, out);
}